// round 2
// baseline (speedup 1.0000x reference)
#include <cuda_runtime.h>

// ---------------------------------------------------------------------------
// MultiLevelClassifier: 3-level routed MLP classifier.
// Key algorithmic win vs reference: only compute the ROUTED expert per row
// at levels 2 and 3 (reference computes all 16 / all 128 experts).
//
// Pipeline (4 launches, same stream, graph-capturable, no allocations):
//   k_init : zero routing counters
//   k_l1   : level-1 head on x for all rows -> logits1, idx1, scatter rows
//            into per-class lists for level 2
//   k_l2   : per level-1 class, gathered rows, head on 0.6x+0.4y -> logits2,
//            idx2, scatter rows into per-(idx1,idx2) lists for level 3
//   k_l3   : per flat expert (128), gathered rows, head on x -> logits3
//
// Inner GEMM: block = 256 threads (one E-column each), R=8 rows cached in
// smem, weights streamed from GMEM coalesced. Math uses fma.rn.f32x2 packed
// along the f (reduction) dimension: features load as natural LDS.64 pairs,
// two weight rows per iteration -> 2x fp32 pipe throughput vs FFMA-3reg.
// ---------------------------------------------------------------------------

#define BB   1024   // batch
#define FF   1024   // feature dim
#define EE   256    // hidden dim
#define L1C  16
#define L2C  8
#define L3C  32
#define NE3  128    // L1C * L2C
#define RCH  8      // rows per chunk

// scratch (device globals: no allocation allowed)
__device__ int g_cnt2[L1C];
__device__ int g_cnt3[NE3];
__device__ int g_rows2[L1C * BB];
__device__ int g_rows3[NE3 * BB];

// ---- packed f32x2 helpers (sm_103a) ---------------------------------------
__device__ __forceinline__ unsigned long long pack2f(float a, float b) {
    unsigned long long r;
    asm("mov.b64 %0, {%1, %2};" : "=l"(r) : "f"(a), "f"(b));
    return r;
}
__device__ __forceinline__ void fma_f32x2(unsigned long long& d,
                                          unsigned long long a,
                                          unsigned long long b) {
    asm("fma.rn.f32x2 %0, %1, %2, %0;" : "+l"(d) : "l"(a), "l"(b));
}
__device__ __forceinline__ float unpack_sum(unsigned long long v) {
    float lo, hi;
    asm("mov.b64 {%0, %1}, %2;" : "=f"(lo), "=f"(hi) : "l"(v));
    return lo + hi;
}

struct Smem {
    float feat[RCH][FF];   // 32 KB  row features
    float act [RCH][EE];   // 8 KB   relu(LN(h))
    float reds[RCH][8];
    float redq[RCH][8];
    float mean[RCH];
    float rstd[RCH];
    float lg  [RCH][32];   // logits (max L = 32)
};

// ---------------------------------------------------------------------------
// One chunk of up to RCH rows through a single expert head:
//   h = feat @ W1 ; act = relu(LN(h)*g+b) ; logits = act @ W2 + b2
//   optional argmax -> scatter row into next-level list
// rowids == nullptr -> rows are b0..b0+nr-1 (level 1 dense case)
// ---------------------------------------------------------------------------
template <int L>
__device__ __forceinline__ void run_mlp(
    Smem& sm, int nr, const int* __restrict__ rowids, int b0,
    const float* __restrict__ fx, const float* __restrict__ fy,
    float alpha, float beta,
    const float* __restrict__ W1,  // [FF, EE] row-major (f major)
    const float* __restrict__ gg, const float* __restrict__ bbv,
    const float* __restrict__ W2,  // [EE, L]
    const float* __restrict__ b2,
    float* __restrict__ logits_out,          // row b written at b*L
    int* __restrict__ cnt_next, int* __restrict__ rows_next, int next_base)
{
    const int tid = threadIdx.x;

    // ---- load features into smem (one float4 per thread per row) ----------
    #pragma unroll
    for (int r = 0; r < RCH; r++) {
        int rr = (r < nr) ? r : 0;                      // clamp: keep data finite
        int b  = rowids ? rowids[rr] : (b0 + rr);
        const float4* sx = (const float4*)(fx + (size_t)b * FF);
        float4 v = sx[tid];
        if (fy) {
            const float4* sy = (const float4*)(fy + (size_t)b * FF);
            float4 u = sy[tid];
            v.x = alpha * v.x + beta * u.x;
            v.y = alpha * v.y + beta * u.y;
            v.z = alpha * v.z + beta * u.z;
            v.w = alpha * v.w + beta * u.w;
        }
        ((float4*)sm.feat[r])[tid] = v;
    }
    __syncthreads();

    // ---- main GEMM: thread tid owns column tid of h -----------------------
    unsigned long long acc[RCH];
    #pragma unroll
    for (int r = 0; r < RCH; r++) acc[r] = 0ull;

    const float* Wp = W1 + tid;            // column tid, stride EE
    #pragma unroll 4
    for (int fp = 0; fp < FF / 2; fp++) {
        float w0 = Wp[(2 * fp) * EE];
        float w1 = Wp[(2 * fp + 1) * EE];
        unsigned long long wv = pack2f(w0, w1);
        #pragma unroll
        for (int r = 0; r < RCH; r++) {
            unsigned long long fv =
                *(const unsigned long long*)&sm.feat[r][2 * fp];
            fma_f32x2(acc[r], fv, wv);
        }
    }
    float h[RCH];
    #pragma unroll
    for (int r = 0; r < RCH; r++) h[r] = unpack_sum(acc[r]);

    // ---- LayerNorm reductions over EE=256 per row -------------------------
    const int lane = tid & 31, wid = tid >> 5;
    #pragma unroll
    for (int r = 0; r < RCH; r++) {
        float s = h[r], q = h[r] * h[r];
        #pragma unroll
        for (int o = 16; o; o >>= 1) {
            s += __shfl_xor_sync(0xffffffffu, s, o);
            q += __shfl_xor_sync(0xffffffffu, q, o);
        }
        if (lane == 0) { sm.reds[r][wid] = s; sm.redq[r][wid] = q; }
    }
    __syncthreads();
    if (tid < RCH) {
        float s = 0.f, q = 0.f;
        #pragma unroll
        for (int w = 0; w < 8; w++) { s += sm.reds[tid][w]; q += sm.redq[tid][w]; }
        float m   = s * (1.0f / EE);
        float var = q * (1.0f / EE) - m * m;
        sm.mean[tid] = m;
        sm.rstd[tid] = rsqrtf(var + 1e-5f);
    }
    __syncthreads();

    const float gt = gg[tid], bt = bbv[tid];
    #pragma unroll
    for (int r = 0; r < RCH; r++) {
        float y = (h[r] - sm.mean[r]) * sm.rstd[r] * gt + bt;
        sm.act[r][tid] = fmaxf(y, 0.0f);
    }
    __syncthreads();

    // ---- second matmul: logits[r][c], thread = (r,c) ----------------------
    if (tid < nr * L) {
        int r = tid / L, c = tid % L;
        float a = b2[c];
        const float* ar = sm.act[r];
        #pragma unroll 4
        for (int e = 0; e < EE; e++) a += ar[e] * W2[e * L + c];
        sm.lg[r][c] = a;
        int b = rowids ? rowids[r] : (b0 + r);
        logits_out[(size_t)b * L + c] = a;
    }
    __syncthreads();

    // ---- argmax + scatter into next-level routing list --------------------
    if (cnt_next && tid < nr) {
        float best = sm.lg[tid][0];
        int   bi   = 0;
        #pragma unroll
        for (int c = 1; c < L; c++) {
            float v = sm.lg[tid][c];
            if (v > best) { best = v; bi = c; }
        }
        int b   = rowids ? rowids[tid] : (b0 + tid);
        int e2  = next_base + bi;
        int pos = atomicAdd(&cnt_next[e2], 1);
        rows_next[e2 * BB + pos] = b;
    }
    __syncthreads();   // protect smem reuse across chunk loop iterations
}

// ---------------------------------------------------------------------------
__global__ void k_init() {
    int t = threadIdx.x;
    if (t < L1C) g_cnt2[t] = 0;
    if (t < NE3) g_cnt3[t] = 0;
}

__global__ __launch_bounds__(256) void k_l1(
    const float* __restrict__ x,
    const float* __restrict__ W1, const float* __restrict__ g,
    const float* __restrict__ b,  const float* __restrict__ W2,
    const float* __restrict__ b2, float* __restrict__ out)
{
    __shared__ Smem sm;
    int b0 = blockIdx.x * RCH;
    run_mlp<L1C>(sm, RCH, nullptr, b0, x, nullptr, 1.0f, 0.0f,
                 W1, g, b, W2, b2,
                 out /* logits1 at offset 0 */,
                 g_cnt2, g_rows2, 0);
}

__global__ __launch_bounds__(256) void k_l2(
    const float* __restrict__ x, const float* __restrict__ y,
    const float* __restrict__ W1, const float* __restrict__ g,
    const float* __restrict__ b,  const float* __restrict__ W2,
    const float* __restrict__ b2, float* __restrict__ out)
{
    __shared__ Smem sm;
    const int e = blockIdx.x;          // level-1 class (expert)
    const int s = blockIdx.y;          // chunk slot
    const int nslot = gridDim.y;
    const int cnt = g_cnt2[e];
    int c = s;
    while (c * RCH < cnt) {
        int start = c * RCH;
        int nr = min(RCH, cnt - start);
        run_mlp<L2C>(sm, nr, g_rows2 + e * BB + start, 0,
                     x, y, 0.6f, 0.4f,
                     W1 + (size_t)e * FF * EE, g + e * EE, b + e * EE,
                     W2 + (size_t)e * EE * L2C, b2 + e * L2C,
                     out + (size_t)BB * L1C /* logits2 */,
                     g_cnt3, g_rows3, e * L2C);
        if (s != nslot - 1) break;     // only last slot loops for overflow
        c++;
    }
}

__global__ __launch_bounds__(256) void k_l3(
    const float* __restrict__ x,
    const float* __restrict__ W1, const float* __restrict__ g,
    const float* __restrict__ b,  const float* __restrict__ W2,
    const float* __restrict__ b2, float* __restrict__ out)
{
    __shared__ Smem sm;
    const int e = blockIdx.x;          // flat expert 0..127
    const int s = blockIdx.y;
    const int nslot = gridDim.y;
    const int cnt = g_cnt3[e];
    int c = s;
    while (c * RCH < cnt) {
        int start = c * RCH;
        int nr = min(RCH, cnt - start);
        run_mlp<L3C>(sm, nr, g_rows3 + e * BB + start, 0,
                     x, nullptr, 1.0f, 0.0f,
                     W1 + (size_t)e * FF * EE, g + e * EE, b + e * EE,
                     W2 + (size_t)e * EE * L3C, b2 + e * L3C,
                     out + (size_t)BB * (L1C + L2C) /* logits3 */,
                     nullptr, nullptr, 0);
        if (s != nslot - 1) break;
        c++;
    }
}

// ---------------------------------------------------------------------------
extern "C" void kernel_launch(void* const* d_in, const int* in_sizes, int n_in,
                              void* d_out, int out_size)
{
    const float* x     = (const float*)d_in[0];
    const float* y     = (const float*)d_in[1];
    const float* l1W1  = (const float*)d_in[2];
    const float* l1g   = (const float*)d_in[3];
    const float* l1b   = (const float*)d_in[4];
    const float* l1W2  = (const float*)d_in[5];
    const float* l1b2  = (const float*)d_in[6];
    const float* l2W1  = (const float*)d_in[7];
    const float* l2g   = (const float*)d_in[8];
    const float* l2b   = (const float*)d_in[9];
    const float* l2W2  = (const float*)d_in[10];
    const float* l2b2  = (const float*)d_in[11];
    const float* l3W1  = (const float*)d_in[12];
    const float* l3g   = (const float*)d_in[13];
    const float* l3b   = (const float*)d_in[14];
    const float* l3W2  = (const float*)d_in[15];
    const float* l3b2  = (const float*)d_in[16];
    float* out = (float*)d_out;

    k_init<<<1, 256>>>();
    k_l1<<<BB / RCH, 256>>>(x, l1W1, l1g, l1b, l1W2, l1b2, out);
    k_l2<<<dim3(L1C, 16), 256>>>(x, y, l2W1, l2g, l2b, l2W2, l2b2, out);
    k_l3<<<dim3(NE3, 4), 256>>>(x, l3W1, l3g, l3b, l3W2, l3b2, out);
}

// round 5
// speedup vs baseline: 5.3200x; 5.3200x over previous
#include <cuda_runtime.h>

// ---------------------------------------------------------------------------
// MultiLevelClassifier — routed-expert implementation, round 2.
//
// R1 failure mode (from ncu): per-expert blocks had no parallelism
// (128 working blocks for l3, 16 for l2), occ 16.7%, HBM at 1.6%.
//
// R2 design: split the f reduction across FSEG=8 blocks per (expert,chunk),
// GEMM writes partials to an 8MB device scratch; a separate finish kernel
// reduces partials and runs LN/ReLU/W2/argmax/scatter. ~1-2K concurrent
// blocks per level -> memory-level parallelism -> bandwidth-bound.
// ---------------------------------------------------------------------------

#define BB   1024
#define FF   1024
#define EE   256
#define L1C  16
#define L2C  8
#define L3C  32
#define NE3  128
#define FSEG 8
#define FS   (FF / FSEG)   // 128 features per segment

// scratch (device globals — no allocation allowed)
__device__ int   g_cnt2[L1C];
__device__ int   g_cnt3[NE3];
__device__ int   g_rows2[L1C * BB];
__device__ int   g_rows3[NE3 * BB];
__device__ float g_part[FSEG * BB * EE];   // 8 MB split-K partials

// ---- packed f32x2 helpers (sm_103a) ---------------------------------------
__device__ __forceinline__ unsigned long long pack2f(float a, float b) {
    unsigned long long r;
    asm("mov.b64 %0, {%1, %2};" : "=l"(r) : "f"(a), "f"(b));
    return r;
}
__device__ __forceinline__ void fma_f32x2(unsigned long long& d,
                                          unsigned long long a,
                                          unsigned long long b) {
    asm("fma.rn.f32x2 %0, %1, %2, %0;" : "+l"(d) : "l"(a), "l"(b));
}
__device__ __forceinline__ float unpack_sum(unsigned long long v) {
    float lo, hi;
    asm("mov.b64 {%0, %1}, %2;" : "=f"(lo), "=f"(hi) : "l"(v));
    return lo + hi;
}

// ---------------------------------------------------------------------------
__global__ void k_init() {
    int t = threadIdx.x;
    if (t < L1C) g_cnt2[t] = 0;
    if (t < NE3) g_cnt3[t] = 0;
}

// ---------------------------------------------------------------------------
// Split-K GEMM: block (slot=bx, fseg=by, expert=bz) processes chunks
// c = slot, slot+NS, ... of expert bz's row list; for each chunk computes
// partial h over f-range [fseg*FS, fseg*FS+FS) for all 256 h-columns and
// R rows, writing g_part[fseg][row][col].
// ---------------------------------------------------------------------------
template <int R, bool MIX, bool DENSE>
__global__ __launch_bounds__(256) void k_gemm(
    const float* __restrict__ fx, const float* __restrict__ fy,
    const float* __restrict__ W1base,          // [NEXP][FF][EE]
    const int* __restrict__ rowlists,          // [NEXP][BB] (unused if DENSE)
    const int* __restrict__ cnts)              // [NEXP]     (unused if DENSE)
{
    const int tid  = threadIdx.x;
    const int slot = blockIdx.x, nslot = gridDim.x;
    const int seg  = blockIdx.y;
    const int e    = blockIdx.z;
    const int f0   = seg * FS;
    const int cnt  = DENSE ? BB : cnts[e];
    const float* __restrict__ W1 = W1base + (size_t)e * FF * EE + (size_t)f0 * EE;

    __shared__ float feat[R][FS];

    for (int c = slot; c * R < cnt; c += nslot) {
        const int start = c * R;
        const int nr = min(R, cnt - start);
        const int* rowids = DENSE ? nullptr : (rowlists + e * BB + start);

        // ---- load feature segment: R rows x FS floats --------------------
        #pragma unroll
        for (int i = tid; i < R * FS / 4; i += 256) {
            int r  = i / (FS / 4);
            int j  = (i % (FS / 4)) * 4;
            int rr = (r < nr) ? r : 0;
            int b  = DENSE ? (start + rr) : rowids[rr];
            float4 v = *(const float4*)(fx + (size_t)b * FF + f0 + j);
            if (MIX) {
                float4 u = *(const float4*)(fy + (size_t)b * FF + f0 + j);
                v.x = 0.6f * v.x + 0.4f * u.x;
                v.y = 0.6f * v.y + 0.4f * u.y;
                v.z = 0.6f * v.z + 0.4f * u.z;
                v.w = 0.6f * v.w + 0.4f * u.w;
            }
            *(float4*)&feat[r][j] = v;
        }
        __syncthreads();

        // ---- GEMM: thread tid owns h-column tid --------------------------
        unsigned long long acc[R];
        #pragma unroll
        for (int r = 0; r < R; r++) acc[r] = 0ull;

        const float* Wp = W1 + tid;
        #pragma unroll 8
        for (int fp = 0; fp < FS / 2; fp++) {
            float w0 = Wp[(2 * fp) * EE];
            float w1 = Wp[(2 * fp + 1) * EE];
            unsigned long long wv = pack2f(w0, w1);
            #pragma unroll
            for (int r = 0; r < R; r++)
                fma_f32x2(acc[r], *(const unsigned long long*)&feat[r][2 * fp], wv);
        }

        // ---- write partials ---------------------------------------------
        #pragma unroll
        for (int r = 0; r < R; r++) {
            if (r < nr) {
                int b = DENSE ? (start + r) : rowids[r];
                g_part[((size_t)seg * BB + b) * EE + tid] = unpack_sum(acc[r]);
            }
        }
        __syncthreads();   // feat reuse next chunk
    }
}

// ---------------------------------------------------------------------------
// Finish: reduce partials -> LN -> ReLU -> x W2 + b2 -> logits out,
// argmax -> scatter into next-level routing lists.
// ---------------------------------------------------------------------------
template <int R, int L, bool DENSE>
__global__ __launch_bounds__(256) void k_fin(
    const int* __restrict__ rowlists, const int* __restrict__ cnts,
    const float* __restrict__ gbase, const float* __restrict__ bbase,
    const float* __restrict__ W2base, const float* __restrict__ b2base,
    float* __restrict__ logits_out,
    int* __restrict__ cnt_next, int* __restrict__ rows_next)
{
    const int tid  = threadIdx.x;
    const int slot = blockIdx.x, nslot = gridDim.x;
    const int e    = blockIdx.y;
    const int cnt  = DENSE ? BB : cnts[e];

    const float* __restrict__ gg = gbase  + (size_t)e * EE;
    const float* __restrict__ bv = bbase  + (size_t)e * EE;
    const float* __restrict__ W2 = W2base + (size_t)e * EE * L;
    const float* __restrict__ b2 = b2base + (size_t)e * L;

    __shared__ float act[R][EE];
    __shared__ float reds[R][8], redq[R][8];
    __shared__ float mean[R], rstd[R];
    __shared__ float lg[R][32];

    const int lane = tid & 31, wid = tid >> 5;
    const float gt = gg[tid], bt = bv[tid];

    for (int c = slot; c * R < cnt; c += nslot) {
        const int start = c * R;
        const int nr = min(R, cnt - start);
        const int* rowids = DENSE ? nullptr : (rowlists + e * BB + start);

        // ---- reduce split-K partials ------------------------------------
        float h[R];
        #pragma unroll
        for (int r = 0; r < R; r++) {
            int rr = (r < nr) ? r : 0;
            int b  = DENSE ? (start + rr) : rowids[rr];
            float s = 0.f;
            #pragma unroll
            for (int seg = 0; seg < FSEG; seg++)
                s += g_part[((size_t)seg * BB + b) * EE + tid];
            h[r] = s;
        }

        // ---- LayerNorm stats --------------------------------------------
        #pragma unroll
        for (int r = 0; r < R; r++) {
            float s = h[r], q = h[r] * h[r];
            #pragma unroll
            for (int o = 16; o; o >>= 1) {
                s += __shfl_xor_sync(0xffffffffu, s, o);
                q += __shfl_xor_sync(0xffffffffu, q, o);
            }
            if (lane == 0) { reds[r][wid] = s; redq[r][wid] = q; }
        }
        __syncthreads();
        if (tid < R) {
            float s = 0.f, q = 0.f;
            #pragma unroll
            for (int w = 0; w < 8; w++) { s += reds[tid][w]; q += redq[tid][w]; }
            float m   = s * (1.0f / EE);
            float var = q * (1.0f / EE) - m * m;
            mean[tid] = m;
            rstd[tid] = rsqrtf(var + 1e-5f);
        }
        __syncthreads();

        #pragma unroll
        for (int r = 0; r < R; r++) {
            float y = (h[r] - mean[r]) * rstd[r] * gt + bt;
            act[r][tid] = fmaxf(y, 0.0f);
        }
        __syncthreads();

        // ---- second matmul ----------------------------------------------
        if (tid < nr * L) {
            int r = tid / L, col = tid % L;
            float a = b2[col];
            const float* ar = act[r];
            #pragma unroll 8
            for (int k = 0; k < EE; k++) a += ar[k] * W2[k * L + col];
            lg[r][col] = a;
            int b = DENSE ? (start + r) : rowids[r];
            logits_out[(size_t)b * L + col] = a;
        }
        __syncthreads();

        // ---- argmax + scatter -------------------------------------------
        if (cnt_next && tid < nr) {
            float best = lg[tid][0];
            int   bi   = 0;
            #pragma unroll
            for (int col = 1; col < L; col++) {
                float v = lg[tid][col];
                if (v > best) { best = v; bi = col; }
            }
            int b   = DENSE ? (start + tid) : rowids[tid];
            int nxt = e * L + bi;
            int pos = atomicAdd(&cnt_next[nxt], 1);
            rows_next[nxt * BB + pos] = b;
        }
        __syncthreads();
    }
}

// ---------------------------------------------------------------------------
extern "C" void kernel_launch(void* const* d_in, const int* in_sizes, int n_in,
                              void* d_out, int out_size)
{
    const float* x    = (const float*)d_in[0];
    const float* y    = (const float*)d_in[1];
    const float* l1W1 = (const float*)d_in[2];
    const float* l1g  = (const float*)d_in[3];
    const float* l1b  = (const float*)d_in[4];
    const float* l1W2 = (const float*)d_in[5];
    const float* l1b2 = (const float*)d_in[6];
    const float* l2W1 = (const float*)d_in[7];
    const float* l2g  = (const float*)d_in[8];
    const float* l2b  = (const float*)d_in[9];
    const float* l2W2 = (const float*)d_in[10];
    const float* l2b2 = (const float*)d_in[11];
    const float* l3W1 = (const float*)d_in[12];
    const float* l3g  = (const float*)d_in[13];
    const float* l3b  = (const float*)d_in[14];
    const float* l3W2 = (const float*)d_in[15];
    const float* l3b2 = (const float*)d_in[16];
    float* out = (float*)d_out;

    int* rows2; int* cnt2; int* rows3; int* cnt3;
    cudaGetSymbolAddress((void**)&rows2, g_rows2);
    cudaGetSymbolAddress((void**)&cnt2,  g_cnt2);
    cudaGetSymbolAddress((void**)&rows3, g_rows3);
    cudaGetSymbolAddress((void**)&cnt3,  g_cnt3);

    k_init<<<1, 256>>>();

    // level 1: dense, R=16 (64 chunks), shared W1 -> L2 resident
    k_gemm<16, false, true><<<dim3(64, FSEG, 1), 256>>>(x, nullptr, l1W1,
                                                        nullptr, nullptr);
    k_fin<16, L1C, true><<<dim3(64, 1), 256>>>(nullptr, nullptr,
                                               l1g, l1b, l1W2, l1b2,
                                               out, cnt2, rows2);

    // level 2: 16 experts, mixed features, R=8
    k_gemm<8, true, false><<<dim3(16, FSEG, L1C), 256>>>(x, y, l2W1,
                                                         rows2, cnt2);
    k_fin<8, L2C, false><<<dim3(16, L1C), 256>>>(rows2, cnt2,
                                                 l2g, l2b, l2W2, l2b2,
                                                 out + (size_t)BB * L1C,
                                                 cnt3, rows3);

    // level 3: 128 experts, R=8
    k_gemm<8, false, false><<<dim3(2, FSEG, NE3), 256>>>(x, nullptr, l3W1,
                                                         rows3, cnt3);
    k_fin<8, L3C, false><<<dim3(2, NE3), 256>>>(rows3, cnt3,
                                                l3g, l3b, l3W2, l3b2,
                                                out + (size_t)BB * (L1C + L2C),
                                                nullptr, nullptr);
}